// round 1
// baseline (speedup 1.0000x reference)
#include <cuda_runtime.h>
#include <cuda_bf16.h>
#include <math.h>

// ---------------------------------------------------------------------------
// DARM: head conv -> (conv relu)x2 -> SE -> (conv relu)x2 -> SE -> tail conv
//       -> per-pixel dynamic filtering with 72 fixed 5x5 basis kernels.
// B=8, C=3, H=W=128, F=128, S=8, K=72. All fp32.
// ---------------------------------------------------------------------------

#define H_ 128
#define W_ 128
#define B_ 8
#define F_ 128
#define K_ 72

// Scratch (device globals -- no allocations allowed)
__device__ float g_A[B_ * F_ * H_ * W_];     // 64 MiB
__device__ float g_B[B_ * F_ * H_ * W_];     // 64 MiB (also holds wgt [8,72,128,128])
__device__ float g_mean[B_ * F_];
__device__ float g_scl[B_ * F_];

// ---------------------------------------------------------------------------
// Generic 3x3 conv, pad=1, NCHW, H=W=128.
// Tile: 16x16 spatial x 32 output channels per 256-thread block.
// Input channels processed in chunks of 8 via shared memory.
// Optional per-(b,ci) input scale (fused SE multiply), optional ReLU.
// grid: (64 tiles, ceil(Cout/32), B)   block: 256
// ---------------------------------------------------------------------------
__global__ __launch_bounds__(256, 2)
void conv3x3_kernel(const float* __restrict__ in, const float* __restrict__ w,
                    const float* __restrict__ bias, const float* __restrict__ scale,
                    float* __restrict__ out, int Cin, int Cout, int doRelu)
{
    __shared__ float s_in[8 * 18 * 18];   // 8 ci x 18x18 halo tile
    __shared__ float s_w[32 * 8 * 9];     // 32 co x 8 ci x 9

    const int tid = threadIdx.x;
    const int b   = blockIdx.z;
    const int coG = blockIdx.y;                 // output-channel group (32 each)
    const int ty  = blockIdx.x >> 3;            // tile row   (0..7)
    const int tx  = blockIdx.x & 7;             // tile col   (0..7)
    const int y0  = ty * 16;
    const int x0  = tx * 16;

    // thread -> (4 consecutive co, 8 consecutive px)
    const int co_base = (tid >> 5) * 4;         // 0,4,...,28 (warp-uniform)
    const int pid = tid & 31;
    const int y   = pid >> 1;                   // 0..15
    const int xb  = (pid & 1) * 8;              // 0 or 8

    float acc[4][8];
#pragma unroll
    for (int j = 0; j < 4; j++)
#pragma unroll
        for (int p = 0; p < 8; p++) acc[j][p] = 0.f;

    for (int c0 = 0; c0 < Cin; c0 += 8) {
        __syncthreads();
        // load input halo tile (zero pad at image borders / past Cin)
        for (int idx = tid; idx < 8 * 324; idx += 256) {
            int ci = idx / 324;
            int r  = idx - ci * 324;
            int iy = r / 18, ix = r - iy * 18;
            int gy = y0 - 1 + iy, gx = x0 - 1 + ix;
            int cig = c0 + ci;
            float v = 0.f;
            if (cig < Cin && (unsigned)gy < 128u && (unsigned)gx < 128u) {
                v = in[((b * Cin + cig) * 128 + gy) * 128 + gx];
                if (scale) v *= scale[b * Cin + cig];
            }
            s_in[idx] = v;
        }
        // load weights for this (co-group, ci-chunk)
        for (int idx = tid; idx < 32 * 72; idx += 256) {
            int co = idx / 72;
            int r  = idx - co * 72;
            int ci = r / 9, k = r - ci * 9;
            int cog = coG * 32 + co, cig = c0 + ci;
            float v = 0.f;
            if (cog < Cout && cig < Cin) v = w[(cog * Cin + cig) * 9 + k];
            s_w[idx] = v;
        }
        __syncthreads();

#pragma unroll 2
        for (int ci = 0; ci < 8; ci++) {
#pragma unroll
            for (int ky = 0; ky < 3; ky++) {
                float r[10];
                const float* row = &s_in[ci * 324 + (y + ky) * 18 + xb];
#pragma unroll
                for (int i = 0; i < 10; i++) r[i] = row[i];
#pragma unroll
                for (int kx = 0; kx < 3; kx++) {
#pragma unroll
                    for (int j = 0; j < 4; j++) {
                        float wv = s_w[(co_base + j) * 72 + ci * 9 + ky * 3 + kx];
#pragma unroll
                        for (int p = 0; p < 8; p++)
                            acc[j][p] = fmaf(wv, r[p + kx], acc[j][p]);
                    }
                }
            }
        }
    }

    // epilogue: bias (+ relu) and store
#pragma unroll
    for (int j = 0; j < 4; j++) {
        int co = coG * 32 + co_base + j;
        if (co < Cout) {
            float bv = bias[co];
            float* op = &out[((b * Cout + co) * 128 + (y0 + y)) * 128 + x0 + xb];
#pragma unroll
            for (int p = 0; p < 8; p++) {
                float v = acc[j][p] + bv;
                if (doRelu) v = fmaxf(v, 0.f);
                op[p] = v;
            }
        }
    }
}

// ---------------------------------------------------------------------------
// SE: global average pool per (b,c). grid: B*F blocks, 256 threads.
// ---------------------------------------------------------------------------
__global__ void se_pool_kernel(const float* __restrict__ f, float* __restrict__ mean)
{
    int bc = blockIdx.x;
    const float* p = f + (size_t)bc * 16384;
    float s = 0.f;
    for (int i = threadIdx.x; i < 16384; i += 256) s += p[i];
#pragma unroll
    for (int o = 16; o > 0; o >>= 1) s += __shfl_xor_sync(0xffffffffu, s, o);
    __shared__ float sh[8];
    if ((threadIdx.x & 31) == 0) sh[threadIdx.x >> 5] = s;
    __syncthreads();
    if (threadIdx.x == 0) {
        float t = 0.f;
#pragma unroll
        for (int i = 0; i < 8; i++) t += sh[i];
        mean[bc] = t * (1.f / 16384.f);
    }
}

// ---------------------------------------------------------------------------
// SE: 1x1 conv -> relu -> 1x1 conv -> sigmoid. 1 block, 1024 threads.
// w1: [8,128], w2: [128,8]
// ---------------------------------------------------------------------------
__global__ void se_fc_kernel(const float* __restrict__ mean,
                             const float* __restrict__ w1, const float* __restrict__ b1,
                             const float* __restrict__ w2, const float* __restrict__ b2,
                             float* __restrict__ scl)
{
    __shared__ float sm[8][128];
    __shared__ float s1[8][8];
    int t = threadIdx.x;
    sm[t >> 7][t & 127] = mean[t];
    __syncthreads();
    if (t < 64) {
        int bb = t >> 3, j = t & 7;
        float a = b1[j];
#pragma unroll 4
        for (int c = 0; c < 128; c++) a = fmaf(w1[j * 128 + c], sm[bb][c], a);
        s1[bb][j] = fmaxf(a, 0.f);
    }
    __syncthreads();
    int bb = t >> 7, co = t & 127;
    float a = b2[co];
#pragma unroll
    for (int j = 0; j < 8; j++) a = fmaf(w2[co * 8 + j], s1[bb][j], a);
    scl[t] = 1.f / (1.f + expf(-a));
}

// ---------------------------------------------------------------------------
// Dynamic filtering: per pixel build effective 5x5 kernel
//   e[p] = sum_k wgt[b,k,y,x] * basis[k,p]
// then out[b,c,y,x] = sum_p e[p] * x_reflectpad[b,c,y+dy-2,x+dx-2]
// grid: (64 row-pairs, B), block 256 (2 rows x 128 cols)
// ---------------------------------------------------------------------------
__global__ __launch_bounds__(256)
void dynfilter_kernel(const float* __restrict__ x, const float* __restrict__ wgt,
                      const float* __restrict__ basis, float* __restrict__ out)
{
    __shared__ float kb[K_ * 25];
    for (int i = threadIdx.x; i < K_ * 25; i += 256) kb[i] = basis[i];
    __syncthreads();

    int b = blockIdx.y;
    int y = blockIdx.x * 2 + (threadIdx.x >> 7);
    int xc = threadIdx.x & 127;

    float e[25];
#pragma unroll
    for (int p = 0; p < 25; p++) e[p] = 0.f;

    for (int k = 0; k < K_; k++) {
        float wv = wgt[((b * K_ + k) * 128 + y) * 128 + xc];
#pragma unroll
        for (int p = 0; p < 25; p++) e[p] = fmaf(wv, kb[k * 25 + p], e[p]);
    }

#pragma unroll
    for (int c = 0; c < 3; c++) {
        float acc = 0.f;
#pragma unroll
        for (int dy = 0; dy < 5; dy++) {
            int yy = y + dy - 2;
            yy = (yy < 0) ? -yy : ((yy > 127) ? 254 - yy : yy);   // reflect
            const float* xr = &x[((b * 3 + c) * 128 + yy) * 128];
#pragma unroll
            for (int dx = 0; dx < 5; dx++) {
                int xx = xc + dx - 2;
                xx = (xx < 0) ? -xx : ((xx > 127) ? 254 - xx : xx);
                acc = fmaf(e[dy * 5 + dx], xr[xx], acc);
            }
        }
        out[((b * 3 + c) * 128 + y) * 128 + xc] = acc;
    }
}

// ---------------------------------------------------------------------------
extern "C" void kernel_launch(void* const* d_in, const int* in_sizes, int n_in,
                              void* d_out, int out_size)
{
    const float* x      = (const float*)d_in[0];
    const float* w_head = (const float*)d_in[1];
    const float* b_head = (const float*)d_in[2];
    const float* w_h1a  = (const float*)d_in[3];
    const float* b_h1a  = (const float*)d_in[4];
    const float* w_h1b  = (const float*)d_in[5];
    const float* b_h1b  = (const float*)d_in[6];
    const float* du1_w1 = (const float*)d_in[7];
    const float* du1_b1 = (const float*)d_in[8];
    const float* du1_w2 = (const float*)d_in[9];
    const float* du1_b2 = (const float*)d_in[10];
    const float* w_h2a  = (const float*)d_in[11];
    const float* b_h2a  = (const float*)d_in[12];
    const float* w_h2b  = (const float*)d_in[13];
    const float* b_h2b  = (const float*)d_in[14];
    const float* du2_w1 = (const float*)d_in[15];
    const float* du2_b1 = (const float*)d_in[16];
    const float* du2_w2 = (const float*)d_in[17];
    const float* du2_b2 = (const float*)d_in[18];
    const float* w_tail = (const float*)d_in[19];
    const float* b_tail = (const float*)d_in[20];
    const float* basis  = (const float*)d_in[21];

    float *A, *Bb, *mean, *scl;
    cudaGetSymbolAddress((void**)&A,    g_A);
    cudaGetSymbolAddress((void**)&Bb,   g_B);
    cudaGetSymbolAddress((void**)&mean, g_mean);
    cudaGetSymbolAddress((void**)&scl,  g_scl);

    dim3 gridF(64, 4, B_);   // 128 output channels
    dim3 gridT(64, 3, B_);   // 72 output channels (ceil(72/32)=3)

    // head (no relu)
    conv3x3_kernel<<<gridF, 256>>>(x, w_head, b_head, nullptr, A, 3, 128, 0);
    // block 1
    conv3x3_kernel<<<gridF, 256>>>(A, w_h1a, b_h1a, nullptr, Bb, 128, 128, 1);
    conv3x3_kernel<<<gridF, 256>>>(Bb, w_h1b, b_h1b, nullptr, A, 128, 128, 1);
    // SE 1 (scale fused into next conv's input read)
    se_pool_kernel<<<B_ * F_, 256>>>(A, mean);
    se_fc_kernel<<<1, 1024>>>(mean, du1_w1, du1_b1, du1_w2, du1_b2, scl);
    // block 2
    conv3x3_kernel<<<gridF, 256>>>(A, w_h2a, b_h2a, scl, Bb, 128, 128, 1);
    conv3x3_kernel<<<gridF, 256>>>(Bb, w_h2b, b_h2b, nullptr, A, 128, 128, 1);
    // SE 2
    se_pool_kernel<<<B_ * F_, 256>>>(A, mean);
    se_fc_kernel<<<1, 1024>>>(mean, du2_w1, du2_b1, du2_w2, du2_b2, scl);
    // tail conv (no relu), wgt -> g_B
    conv3x3_kernel<<<gridT, 256>>>(A, w_tail, b_tail, scl, Bb, 128, 72, 0);
    // dynamic filtering
    dynfilter_kernel<<<dim3(64, B_), 256>>>(x, Bb, basis, (float*)d_out);
}

// round 5
// speedup vs baseline: 2.5297x; 2.5297x over previous
#include <cuda_runtime.h>
#include <cuda_bf16.h>
#include <math.h>
#include <cstdint>

// ===========================================================================
// DARM on GB300 (base sm_103 ISA): split-bf16 (3-term) mma.sync implicit-GEMM
// convs + fp32 head conv + SE + per-pixel dynamic filtering.
// B=8, C=3, H=W=128, F=128, S=8, K=72.
// Activations between mma convs live in global memory PRE-SPLIT:
//   hi/lo bf16 planes, packed b32 = (bf16 of chan c | bf16 of chan c+8 << 16),
//   layout [b][g=ci/16][p=ci%8][y][x], lo plane at +LO_OFF.
// ===========================================================================

#define B_ 8
#define F_ 128
#define K_ 72
#define LO_OFF 8388608u   // b32 offset of lo plane (8*8*8*16384)

__device__ unsigned g_A[16777216];           // 64 MiB  (split act / ping)
__device__ unsigned g_B[16777216];           // 64 MiB  (split act / pong; also fp32 head & tail wgt)
__device__ float    g_mean[B_ * F_];
__device__ float    g_scl[B_ * F_];
__device__ unsigned g_Wt[5 * 147456];        // per conv: [t 24][plane 2][pair 24][co 128] b32

// ---------------------------------------------------------------------------
// helpers
// ---------------------------------------------------------------------------
__device__ __forceinline__ uint32_t smem_u32(const void* p) {
    uint32_t a;
    asm("{ .reg .u64 t; cvta.to.shared.u64 t, %1; cvt.u32.u64 %0, t; }" : "=r"(a) : "l"(p));
    return a;
}
__device__ __forceinline__ void cpa16(uint32_t d, const void* s) {
    asm volatile("cp.async.cg.shared.global [%0], [%1], 16;" :: "r"(d), "l"(s) : "memory");
}
__device__ __forceinline__ void cpa4(uint32_t d, const void* s, int sz) {
    asm volatile("cp.async.ca.shared.global [%0], [%1], 4, %2;" :: "r"(d), "l"(s), "r"(sz) : "memory");
}
#define CP_COMMIT() asm volatile("cp.async.commit_group;" ::: "memory")
#define CP_WAIT0()  asm volatile("cp.async.wait_group 0;" ::: "memory")

#define MMA_BF16(d, a, bb) \
    asm volatile("mma.sync.aligned.m16n8k16.row.col.f32.bf16.bf16.f32 " \
        "{%0,%1,%2,%3},{%4,%5,%6,%7},{%8,%9},{%0,%1,%2,%3};" \
        : "+f"((d)[0]), "+f"((d)[1]), "+f"((d)[2]), "+f"((d)[3]) \
        : "r"((a)[0]), "r"((a)[1]), "r"((a)[2]), "r"((a)[3]), "r"((bb)[0]), "r"((bb)[1]))

__device__ __forceinline__ uint32_t bfb(float v) {
    return (uint32_t)__bfloat16_as_ushort(__float2bfloat16(v));
}
__device__ __forceinline__ float bff(uint32_t b) { return __uint_as_float(b << 16); }
__device__ __forceinline__ void split2(float v, uint32_t& h, uint32_t& l) {
    h = bfb(v);
    l = bfb(v - bff(h));
}

// ---------------------------------------------------------------------------
// Weight repack: w[Cout][128][3][3] fp32 -> split/packed
// out[t=cg*3+ky][plane hi/lo][pidx=kx*8+p][co], b32 = (ci=cg*16+p | ci+8 <<16)
// grid 576 (= t*24 + pidx), block 128 (co)
// ---------------------------------------------------------------------------
__global__ void repack_w_kernel(const float* __restrict__ w, unsigned* __restrict__ wt, int Cout)
{
    int t = blockIdx.x / 24, pidx = blockIdx.x % 24;
    int cg = t / 3, ky = t - cg * 3;
    int kx = pidx >> 3, p = pidx & 7;
    int co = threadIdx.x;
    int ci0 = cg * 16 + p, ci1 = ci0 + 8;
    float v0 = 0.f, v1 = 0.f;
    if (co < Cout) {
        v0 = w[co * 1152 + ci0 * 9 + ky * 3 + kx];
        v1 = w[co * 1152 + ci1 * 9 + ky * 3 + kx];
    }
    uint32_t h0, l0, h1, l1;
    split2(v0, h0, l0); split2(v1, h1, l1);
    wt[((t * 2 + 0) * 24 + pidx) * 128 + co] = h0 | (h1 << 16);
    wt[((t * 2 + 1) * 24 + pidx) * 128 + co] = l0 | (l1 << 16);
}

// ---------------------------------------------------------------------------
// split-bf16 mma conv, Cin=128. CTA: M=128 co x N=256 px (2 rows). 8 warps.
// K = 1152: 24 chunks (cg,ky) x 3 kx x 16 ci. 3 MMAs per (hi*hi,hi*lo,lo*hi).
// smem b32: A bufs 2 x [2 plane][24 pair][136]  (6528 each)
//           B bufs 2 x [2 plane][8 pair][4 rs][138] (8832 each)
// grid (64 row-pairs, 8 batch)
// ---------------------------------------------------------------------------
#define AFU 6528
#define BFU 8832
#define CONV_SMEM ((2 * AFU + 2 * BFU) * 4)   // 122880 B

__global__ __launch_bounds__(256, 1)
void conv_mma_kernel(const unsigned* __restrict__ actin, const unsigned* __restrict__ wt,
                     const float* __restrict__ bias, void* __restrict__ outp,
                     int Cout, int doRelu, int splitOut)
{
    extern __shared__ unsigned sm32[];
    const uint32_t sb = smem_u32(sm32);

    const int tid  = threadIdx.x;
    const int wid  = tid >> 5;
    const int lane = tid & 31;
    const int tid4 = lane & 3;
    const int grp  = lane >> 2;
    const int m0 = (wid >> 2) * 64;
    const int n0 = (wid & 3) * 64;
    const int b  = blockIdx.y;
    const int y0 = blockIdx.x * 2;

    int nb[8];
#pragma unroll
    for (int nf = 0; nf < 8; nf++) {
        int n = n0 + nf * 8 + grp;
        nb[nf] = (n >> 7) * 138 + (n & 127);
    }

    float d[4][8][4];
#pragma unroll
    for (int mt = 0; mt < 4; mt++)
#pragma unroll
        for (int nf = 0; nf < 8; nf++)
#pragma unroll
            for (int i = 0; i < 4; i++) d[mt][nf][i] = 0.f;

    auto loadA = [&](int t, int buf) {
        const unsigned* src = wt + t * 6144;
        const uint32_t dst = sb + (buf ? AFU * 4u : 0u);
#pragma unroll
        for (int i = tid; i < 1536; i += 256) {
            int plane = i / 768, rem = i - plane * 768;
            int pair = rem >> 5, co4 = (rem & 31) << 2;
            cpa16(dst + (uint32_t)(plane * 3264 + pair * 136 + co4) * 4u,
                  src + plane * 3072 + pair * 128 + co4);
        }
    };
    auto loadB = [&](int cg, int buf) {
        const uint32_t dst = sb + (uint32_t)(2 * AFU + (buf ? BFU : 0)) * 4u;
        const unsigned* basep = actin + ((size_t)b * 8 + cg) * 8 * 16384;
        for (int i = tid; i < 8448; i += 256) {
            int plane = i / 4224, rem = i - plane * 4224;
            int pair = rem / 528, r2 = rem - pair * 528;
            int rs = r2 / 132, xs = r2 - rs * 132;
            int y = y0 - 1 + rs, xi = xs - 1;
            bool ok = ((unsigned)y < 128u) && ((unsigned)xi < 128u);
            const unsigned* src = basep + (size_t)plane * LO_OFF + pair * 16384
                                + (ok ? (y * 128 + xi) : 0);
            cpa4(dst + (uint32_t)(plane * 4416 + pair * 552 + rs * 138 + xs) * 4u,
                 src, ok ? 4 : 0);
        }
    };

    loadB(0, 0);
    loadA(0, 0);
    CP_COMMIT();

    for (int t = 0; t < 24; ++t) {
        const int cg = t / 3;
        const int ky = t - cg * 3;
        CP_WAIT0();
        __syncthreads();
        if (t < 23) {
            loadA(t + 1, (t + 1) & 1);
            if (ky == 2) loadB(cg + 1, (cg + 1) & 1);
            CP_COMMIT();
        }
        const unsigned* As = sm32 + (t & 1) * AFU;
        const unsigned* Bs = sm32 + 2 * AFU + (cg & 1) * BFU;
        const int kyo = ky * 138;

#pragma unroll
        for (int kx = 0; kx < 3; ++kx) {
            // A: pairs laid out as pidx = kx*8 + p (24 pairs/plane)
            const unsigned* Ah = As + (kx * 8 + tid4) * 136 + m0 + grp;
            const unsigned* Al = Ah + 3264;
            uint32_t ah[4][4], al[4][4];
#pragma unroll
            for (int mt = 0; mt < 4; mt++) {
                ah[mt][0] = Ah[mt * 16];       ah[mt][1] = Ah[mt * 16 + 8];
                ah[mt][2] = Ah[mt * 16 + 544]; ah[mt][3] = Ah[mt * 16 + 552];
                al[mt][0] = Al[mt * 16];       al[mt][1] = Al[mt * 16 + 8];
                al[mt][2] = Al[mt * 16 + 544]; al[mt][3] = Al[mt * 16 + 552];
            }
            // B: only 8 ci-pairs/plane; kx handled by the +kx x-shift.
            // b0 = pair tid4, b1 = pair tid4+4 (+2208 = 4*552).
            const unsigned* Bh = Bs + tid4 * 552 + kyo + kx;
            const unsigned* Bl = Bh + 4416;
#pragma unroll
            for (int nf = 0; nf < 8; nf++) {
                uint32_t bh[2] = { Bh[nb[nf]], Bh[nb[nf] + 2208] };
                uint32_t bl[2] = { Bl[nb[nf]], Bl[nb[nf] + 2208] };
#pragma unroll
                for (int mt = 0; mt < 4; mt++) {
                    MMA_BF16(d[mt][nf], ah[mt], bh);
                    MMA_BF16(d[mt][nf], ah[mt], bl);
                    MMA_BF16(d[mt][nf], al[mt], bh);
                }
            }
        }
    }

    // ---- epilogue ----
    if (splitOut) {
        unsigned* outu = (unsigned*)outp;
#pragma unroll
        for (int mt = 0; mt < 4; mt++) {
            const int co0 = m0 + mt * 16 + grp;       // co0 & 15 == grp < 8
            const int g = co0 >> 4;
            const float bv0 = bias[co0], bv1 = bias[co0 + 8];
            const size_t cpb = (((size_t)b * 8 + g) * 8 + grp) * 16384;
#pragma unroll
            for (int nf = 0; nf < 8; nf++) {
                const int n = n0 + nf * 8 + 2 * tid4;
                const int pix = (y0 + (n >> 7)) * 128 + (n & 127);
                float v0 = d[mt][nf][0] + bv0, v1 = d[mt][nf][1] + bv0;
                float v2 = d[mt][nf][2] + bv1, v3 = d[mt][nf][3] + bv1;
                if (doRelu) {
                    v0 = fmaxf(v0, 0.f); v1 = fmaxf(v1, 0.f);
                    v2 = fmaxf(v2, 0.f); v3 = fmaxf(v3, 0.f);
                }
                uint32_t h0, l0, h1, l1, h2, l2, h3, l3;
                split2(v0, h0, l0); split2(v1, h1, l1);
                split2(v2, h2, l2); split2(v3, h3, l3);
                uint2* ph = (uint2*)(outu + cpb + pix);
                uint2* pl = (uint2*)(outu + LO_OFF + cpb + pix);
                *ph = make_uint2(h0 | (h2 << 16), h1 | (h3 << 16));
                *pl = make_uint2(l0 | (l2 << 16), l1 | (l3 << 16));
            }
        }
    } else {
        float* outf = (float*)outp;
#pragma unroll
        for (int mt = 0; mt < 4; mt++) {
            const int co0 = m0 + mt * 16 + grp;
            const int co1 = co0 + 8;
            const float bv0 = (co0 < Cout) ? bias[co0] : 0.f;
            const float bv1 = (co1 < Cout) ? bias[co1] : 0.f;
#pragma unroll
            for (int nf = 0; nf < 8; nf++) {
                const int n = n0 + nf * 8 + 2 * tid4;
                const int y = y0 + (n >> 7), x = n & 127;
                if (co0 < Cout) {
                    float v0 = d[mt][nf][0] + bv0, v1 = d[mt][nf][1] + bv0;
                    if (doRelu) { v0 = fmaxf(v0, 0.f); v1 = fmaxf(v1, 0.f); }
                    *(float2*)(outf + (((size_t)b * Cout + co0) * 128 + y) * 128 + x)
                        = make_float2(v0, v1);
                }
                if (co1 < Cout) {
                    float v2 = d[mt][nf][2] + bv1, v3 = d[mt][nf][3] + bv1;
                    if (doRelu) { v2 = fmaxf(v2, 0.f); v3 = fmaxf(v3, 0.f); }
                    *(float2*)(outf + (((size_t)b * Cout + co1) * 128 + y) * 128 + x)
                        = make_float2(v2, v3);
                }
            }
        }
    }
}

// ---------------------------------------------------------------------------
// fp32 head conv (Cin=3, Cout=128), plain fp32 output
// ---------------------------------------------------------------------------
__global__ __launch_bounds__(256, 2)
void conv3x3_kernel(const float* __restrict__ in, const float* __restrict__ w,
                    const float* __restrict__ bias, float* __restrict__ out,
                    int Cin, int Cout)
{
    __shared__ float s_in[8 * 18 * 18];
    __shared__ float s_w[32 * 8 * 9];
    const int tid = threadIdx.x;
    const int b   = blockIdx.z;
    const int coG = blockIdx.y;
    const int ty  = blockIdx.x >> 3;
    const int tx  = blockIdx.x & 7;
    const int y0 = ty * 16, x0 = tx * 16;
    const int co_base = (tid >> 5) * 4;
    const int pid = tid & 31;
    const int y  = pid >> 1;
    const int xb = (pid & 1) * 8;

    float acc[4][8];
#pragma unroll
    for (int j = 0; j < 4; j++)
#pragma unroll
        for (int p = 0; p < 8; p++) acc[j][p] = 0.f;

    for (int c0 = 0; c0 < Cin; c0 += 8) {
        __syncthreads();
        for (int idx = tid; idx < 8 * 324; idx += 256) {
            int ci = idx / 324;
            int r  = idx - ci * 324;
            int iy = r / 18, ix = r - iy * 18;
            int gy = y0 - 1 + iy, gx = x0 - 1 + ix;
            int cig = c0 + ci;
            float v = 0.f;
            if (cig < Cin && (unsigned)gy < 128u && (unsigned)gx < 128u)
                v = in[((b * Cin + cig) * 128 + gy) * 128 + gx];
            s_in[idx] = v;
        }
        for (int idx = tid; idx < 32 * 72; idx += 256) {
            int co = idx / 72;
            int r  = idx - co * 72;
            int ci = r / 9, k = r - ci * 9;
            int cog = coG * 32 + co, cig = c0 + ci;
            float v = 0.f;
            if (cog < Cout && cig < Cin) v = w[(cog * Cin + cig) * 9 + k];
            s_w[idx] = v;
        }
        __syncthreads();
#pragma unroll 2
        for (int ci = 0; ci < 8; ci++) {
#pragma unroll
            for (int ky = 0; ky < 3; ky++) {
                float r[10];
                const float* row = &s_in[ci * 324 + (y + ky) * 18 + xb];
#pragma unroll
                for (int i = 0; i < 10; i++) r[i] = row[i];
#pragma unroll
                for (int kx = 0; kx < 3; kx++) {
#pragma unroll
                    for (int j = 0; j < 4; j++) {
                        float wv = s_w[(co_base + j) * 72 + ci * 9 + ky * 3 + kx];
#pragma unroll
                        for (int p = 0; p < 8; p++)
                            acc[j][p] = fmaf(wv, r[p + kx], acc[j][p]);
                    }
                }
            }
        }
    }
#pragma unroll
    for (int j = 0; j < 4; j++) {
        int co = coG * 32 + co_base + j;
        if (co < Cout) {
            float bv = bias[co];
            float* op = &out[((b * Cout + co) * 128 + (y0 + y)) * 128 + x0 + xb];
#pragma unroll
            for (int p = 0; p < 8; p++) op[p] = acc[j][p] + bv;
        }
    }
}

// ---------------------------------------------------------------------------
// convert fp32 NCHW activation -> split packed planes. grid 32768, block 256.
// ---------------------------------------------------------------------------
__global__ void convert_split_kernel(const float* __restrict__ in, unsigned* __restrict__ out)
{
    unsigned i = blockIdx.x * 256 + threadIdx.x;   // 0..8388607
    unsigned cp = i >> 14, pix = i & 16383u;
    unsigned b = cp >> 6, g = (cp >> 3) & 7u, p = cp & 7u;
    unsigned c0 = g * 16 + p;
    float v0 = in[((size_t)b * 128 + c0) * 16384 + pix];
    float v1 = in[((size_t)b * 128 + c0 + 8) * 16384 + pix];
    uint32_t h0, l0, h1, l1;
    split2(v0, h0, l0); split2(v1, h1, l1);
    out[i] = h0 | (h1 << 16);
    out[LO_OFF + i] = l0 | (l1 << 16);
}

// ---------------------------------------------------------------------------
// SE on split activations
// ---------------------------------------------------------------------------
__global__ void se_pool_split_kernel(const unsigned* __restrict__ act, float* __restrict__ mean)
{
    int bc = blockIdx.x;               // b*128 + c
    int b = bc >> 7, c = bc & 127;
    int g = c >> 4, pl = c & 15, p = pl & 7;
    int sh = (pl >= 8) ? 16 : 0;
    const unsigned* ph = act + (((size_t)b * 8 + g) * 8 + p) * 16384;
    float s = 0.f;
    for (int i = threadIdx.x; i < 16384; i += 256) {
        s += bff((ph[i] >> sh) & 0xffffu);
        s += bff((ph[LO_OFF + i] >> sh) & 0xffffu);
    }
#pragma unroll
    for (int o = 16; o > 0; o >>= 1) s += __shfl_xor_sync(0xffffffffu, s, o);
    __shared__ float shm[8];
    if ((threadIdx.x & 31) == 0) shm[threadIdx.x >> 5] = s;
    __syncthreads();
    if (threadIdx.x == 0) {
        float t = 0.f;
#pragma unroll
        for (int i = 0; i < 8; i++) t += shm[i];
        mean[bc] = t * (1.f / 16384.f);
    }
}

__global__ void se_fc_kernel(const float* __restrict__ mean,
                             const float* __restrict__ w1, const float* __restrict__ b1,
                             const float* __restrict__ w2, const float* __restrict__ b2,
                             float* __restrict__ scl)
{
    __shared__ float smn[8][128];
    __shared__ float s1[8][8];
    int t = threadIdx.x;
    smn[t >> 7][t & 127] = mean[t];
    __syncthreads();
    if (t < 64) {
        int bb = t >> 3, j = t & 7;
        float a = b1[j];
#pragma unroll 4
        for (int c = 0; c < 128; c++) a = fmaf(w1[j * 128 + c], smn[bb][c], a);
        s1[bb][j] = fmaxf(a, 0.f);
    }
    __syncthreads();
    int bb = t >> 7, co = t & 127;
    float a = b2[co];
#pragma unroll
    for (int j = 0; j < 8; j++) a = fmaf(w2[co * 8 + j], s1[bb][j], a);
    scl[t] = 1.f / (1.f + expf(-a));
}

// in-place scale of split activation. grid 32768, block 256.
__global__ void se_scale_split_kernel(unsigned* __restrict__ act, const float* __restrict__ scl)
{
    unsigned i = blockIdx.x * 256 + threadIdx.x;
    unsigned cp = i >> 14;
    unsigned b = cp >> 6, g = (cp >> 3) & 7u, p = cp & 7u;
    unsigned c0 = g * 16 + p;
    float s0 = scl[b * 128 + c0];
    float s1 = scl[b * 128 + c0 + 8];
    unsigned uh = act[i], ul = act[LO_OFF + i];
    float v0 = (bff(uh & 0xffffu) + bff(ul & 0xffffu)) * s0;
    float v1 = (bff(uh >> 16) + bff(ul >> 16)) * s1;
    uint32_t h0, l0, h1, l1;
    split2(v0, h0, l0); split2(v1, h1, l1);
    act[i] = h0 | (h1 << 16);
    act[LO_OFF + i] = l0 | (l1 << 16);
}

// ---------------------------------------------------------------------------
// Dynamic filtering
// ---------------------------------------------------------------------------
__global__ __launch_bounds__(256)
void dynfilter_kernel(const float* __restrict__ x, const float* __restrict__ wgt,
                      const float* __restrict__ basis, float* __restrict__ out)
{
    __shared__ float kb[K_ * 25];
    for (int i = threadIdx.x; i < K_ * 25; i += 256) kb[i] = basis[i];
    __syncthreads();
    int b = blockIdx.y;
    int y = blockIdx.x * 2 + (threadIdx.x >> 7);
    int xc = threadIdx.x & 127;
    float e[25];
#pragma unroll
    for (int p = 0; p < 25; p++) e[p] = 0.f;
    for (int k = 0; k < K_; k++) {
        float wv = wgt[((b * K_ + k) * 128 + y) * 128 + xc];
#pragma unroll
        for (int p = 0; p < 25; p++) e[p] = fmaf(wv, kb[k * 25 + p], e[p]);
    }
#pragma unroll
    for (int c = 0; c < 3; c++) {
        float acc = 0.f;
#pragma unroll
        for (int dy = 0; dy < 5; dy++) {
            int yy = y + dy - 2;
            yy = (yy < 0) ? -yy : ((yy > 127) ? 254 - yy : yy);
            const float* xr = &x[((b * 3 + c) * 128 + yy) * 128];
#pragma unroll
            for (int dx = 0; dx < 5; dx++) {
                int xx = xc + dx - 2;
                xx = (xx < 0) ? -xx : ((xx > 127) ? 254 - xx : xx);
                acc = fmaf(e[dy * 5 + dx], xr[xx], acc);
            }
        }
        out[((b * 3 + c) * 128 + y) * 128 + xc] = acc;
    }
}

// ---------------------------------------------------------------------------
extern "C" void kernel_launch(void* const* d_in, const int* in_sizes, int n_in,
                              void* d_out, int out_size)
{
    const float* x      = (const float*)d_in[0];
    const float* w_head = (const float*)d_in[1];
    const float* b_head = (const float*)d_in[2];
    const float* w_h1a  = (const float*)d_in[3];
    const float* b_h1a  = (const float*)d_in[4];
    const float* w_h1b  = (const float*)d_in[5];
    const float* b_h1b  = (const float*)d_in[6];
    const float* du1_w1 = (const float*)d_in[7];
    const float* du1_b1 = (const float*)d_in[8];
    const float* du1_w2 = (const float*)d_in[9];
    const float* du1_b2 = (const float*)d_in[10];
    const float* w_h2a  = (const float*)d_in[11];
    const float* b_h2a  = (const float*)d_in[12];
    const float* w_h2b  = (const float*)d_in[13];
    const float* b_h2b  = (const float*)d_in[14];
    const float* du2_w1 = (const float*)d_in[15];
    const float* du2_b1 = (const float*)d_in[16];
    const float* du2_w2 = (const float*)d_in[17];
    const float* du2_b2 = (const float*)d_in[18];
    const float* w_tail = (const float*)d_in[19];
    const float* b_tail = (const float*)d_in[20];
    const float* basis  = (const float*)d_in[21];

    unsigned *A, *Bb, *Wt;
    float *mean, *scl;
    cudaGetSymbolAddress((void**)&A,    g_A);
    cudaGetSymbolAddress((void**)&Bb,   g_B);
    cudaGetSymbolAddress((void**)&mean, g_mean);
    cudaGetSymbolAddress((void**)&scl,  g_scl);
    cudaGetSymbolAddress((void**)&Wt,   g_Wt);

    cudaFuncSetAttribute(conv_mma_kernel,
                         cudaFuncAttributeMaxDynamicSharedMemorySize, CONV_SMEM);

    const int WS = 147456;
    repack_w_kernel<<<576, 128>>>(w_h1a, Wt + 0 * WS, 128);
    repack_w_kernel<<<576, 128>>>(w_h1b, Wt + 1 * WS, 128);
    repack_w_kernel<<<576, 128>>>(w_h2a, Wt + 2 * WS, 128);
    repack_w_kernel<<<576, 128>>>(w_h2b, Wt + 3 * WS, 128);
    repack_w_kernel<<<576, 128>>>(w_tail, Wt + 4 * WS, 72);

    // head (fp32) -> g_B (fp32), then convert to split planes in g_A
    conv3x3_kernel<<<dim3(64, 4, B_), 256>>>(x, w_head, b_head, (float*)Bb, 3, 128);
    convert_split_kernel<<<32768, 256>>>((const float*)Bb, A);

    dim3 cgrid(64, B_);
    // block 1 (split in/out)
    conv_mma_kernel<<<cgrid, 256, CONV_SMEM>>>(A,  Wt + 0 * WS, b_h1a, Bb, 128, 1, 1);
    conv_mma_kernel<<<cgrid, 256, CONV_SMEM>>>(Bb, Wt + 1 * WS, b_h1b, A, 128, 1, 1);
    // SE 1
    se_pool_split_kernel<<<B_ * F_, 256>>>(A, mean);
    se_fc_kernel<<<1, 1024>>>(mean, du1_w1, du1_b1, du1_w2, du1_b2, scl);
    se_scale_split_kernel<<<32768, 256>>>(A, scl);
    // block 2
    conv_mma_kernel<<<cgrid, 256, CONV_SMEM>>>(A,  Wt + 2 * WS, b_h2a, Bb, 128, 1, 1);
    conv_mma_kernel<<<cgrid, 256, CONV_SMEM>>>(Bb, Wt + 3 * WS, b_h2b, A, 128, 1, 1);
    // SE 2
    se_pool_split_kernel<<<B_ * F_, 256>>>(A, mean);
    se_fc_kernel<<<1, 1024>>>(mean, du2_w1, du2_b1, du2_w2, du2_b2, scl);
    se_scale_split_kernel<<<32768, 256>>>(A, scl);
    // tail: split in, fp32 out (72 ch) -> g_B
    conv_mma_kernel<<<cgrid, 256, CONV_SMEM>>>(A, Wt + 4 * WS, b_tail, Bb, 72, 0, 0);
    // dynamic filtering
    dynfilter_kernel<<<dim3(64, B_), 256>>>(x, (const float*)Bb, basis, (float*)d_out);
}